// round 3
// baseline (speedup 1.0000x reference)
#include <cuda_runtime.h>

// GConv: x (N=16, C=64, R=8, H=64, W=64), weight (O=64, C=64, R=8, K=5)
// out (N, O, ROT=8, H, W)
// out[n,o,rot,h,w] = sum_{r,c,k} weight[o,c,(r-rot)&7,k] * xpad[n,c,r,h+dy(k,rot),w+dx(k,rot)]
// taps: k=0 -> (0,0); k>=1 -> RING[(2k-1+rot)&7]

#define TH 8
#define TW 32
#define NTHREADS 256
#define CC 64
#define RR 8
#define OO 64
#define HH 64
#define WW 64
#define SLAB_ROWS (TH + 2)            // 10
#define SLAB_COLS (TW + 2)            // 34
#define RCNT (SLAB_ROWS * SLAB_COLS)  // 340
#define CPAD 65
#define WSLICE (64 * 5 * 64)          // 20480 floats per (s) slice

typedef unsigned long long u64;

// pre-transposed weight: wt[s][c][k][o]
__device__ float4 g_wt4[(64 * 64 * 8 * 5) / 4];

__device__ __forceinline__ u64 pack2(float x) {
    u64 r;
    asm("mov.b64 %0, {%1, %1};" : "=l"(r) : "f"(x));
    return r;
}
__device__ __forceinline__ void ffma2(u64& a, u64 x, u64 w) {
    asm("fma.rn.f32x2 %0, %1, %2, %0;" : "+l"(a) : "l"(x), "l"(w));
}
__device__ __forceinline__ void unpack2(u64 v, float& lo, float& hi) {
    asm("mov.b64 {%0, %1}, %2;" : "=f"(lo), "=f"(hi) : "l"(v));
}

__global__ void wt_transpose(const float* __restrict__ wsrc) {
    int idx = blockIdx.x * blockDim.x + threadIdx.x;  // < 163840
    int o = idx & 63;
    int k = (idx >> 6) % 5;
    int c = (idx / 320) & 63;
    int s = idx / 20480;
    // weight[o][c][s][k] -> wt[s][c][k][o]
    ((float*)g_wt4)[idx] = wsrc[o * 2560 + c * 40 + s * 5 + k];
}

// RING tables as constexpr so tap offsets are compile-time per ROT.
__device__ __forceinline__ constexpr int ring_dy(int i) {
    constexpr int t[8] = {-1, -1, -1, 0, 1, 1, 1, 0};
    return t[i & 7];
}
__device__ __forceinline__ constexpr int ring_dx(int i) {
    constexpr int t[8] = {-1, 0, 1, 1, 1, 0, -1, -1};
    return t[i & 7];
}

template <int ROT>
__device__ __forceinline__ void gconv_body(const float* __restrict__ xg,
                                           float* __restrict__ outg,
                                           float* sx, float* sw) {
    const int n = blockIdx.z;
    const int ht = blockIdx.x >> 1;
    const int wt = blockIdx.x & 1;
    const int h0 = ht * TH;
    const int w0 = wt * TW;

    const int tid = threadIdx.x;
    const int og = tid & 3;     // 16-output group
    const int pg = tid >> 2;    // pixel group 0..63
    const int prow = pg >> 3;   // 0..7
    const int pcg = pg & 7;     // 0..7 -> cols pcg*4..pcg*4+3

    // Compile-time tap offsets within padded slab (row-major, stride SLAB_COLS)
    constexpr int off0 = 1 * SLAB_COLS + 1;
    constexpr int off1 = (ring_dy((1 + ROT) & 7) + 1) * SLAB_COLS + (ring_dx((1 + ROT) & 7) + 1);
    constexpr int off2 = (ring_dy((3 + ROT) & 7) + 1) * SLAB_COLS + (ring_dx((3 + ROT) & 7) + 1);
    constexpr int off3 = (ring_dy((5 + ROT) & 7) + 1) * SLAB_COLS + (ring_dx((5 + ROT) & 7) + 1);
    constexpr int off4 = (ring_dy((7 + ROT) & 7) + 1) * SLAB_COLS + (ring_dx((7 + ROT) & 7) + 1);
    const int offk[5] = {off0, off1, off2, off3, off4};

    const int bp0 = prow * SLAB_COLS + pcg * 4;  // base slab position of this thread

    u64 acc[4][8];
#pragma unroll
    for (int j = 0; j < 4; ++j)
#pragma unroll
        for (int q = 0; q < 8; ++q) acc[j][q] = 0ull;

    for (int r = 0; r < RR; ++r) {
        __syncthreads();
        // ---- stage x plane r: sx[(row*34+col)*65 + c] with zero halo ----
        {
            const float* xp = xg + ((size_t)n * CC * RR + r) * (HH * WW);
            for (int lin = tid; lin < CC * RCNT; lin += NTHREADS) {
                int c = lin / RCNT;
                int rc = lin - c * RCNT;
                int row = rc / SLAB_COLS;
                int col = rc - row * SLAB_COLS;
                int gh = h0 - 1 + row;
                int gw = w0 - 1 + col;
                float v = 0.f;
                if ((unsigned)gh < HH && (unsigned)gw < WW)
                    v = xp[(size_t)c * (RR * HH * WW) + gh * WW + gw];
                sx[rc * CPAD + c] = v;
            }
        }
        // ---- stage weight slice s = (r - rot) & 7 : sw[c][k][o] ----
        {
            int s = (r - ROT) & 7;
            const float4* wsrc4 = g_wt4 + (size_t)s * (WSLICE / 4);
            float4* sw4 = (float4*)sw;
            for (int i = tid; i < WSLICE / 4; i += NTHREADS) sw4[i] = wsrc4[i];
        }
        __syncthreads();

        const float* swb = sw + og * 16;
        const float* sxb = sx + bp0 * CPAD;
#pragma unroll 2
        for (int c = 0; c < CC; ++c) {
            // Load + pack unique x taps (compile-time offsets -> ptxas CSEs
            // overlapping positions across the 4 adjacent pixels)
            u64 xv[4][5];
#pragma unroll
            for (int j = 0; j < 4; ++j)
#pragma unroll
                for (int k = 0; k < 5; ++k)
                    xv[j][k] = pack2(sxb[(j + offk[k]) * CPAD + c]);

#pragma unroll
            for (int k = 0; k < 5; ++k) {
                const ulonglong2* wp =
                    (const ulonglong2*)(swb + c * 320 + k * 64);
                ulonglong2 q0 = wp[0];
                ulonglong2 q1 = wp[1];
                ulonglong2 q2 = wp[2];
                ulonglong2 q3 = wp[3];
#pragma unroll
                for (int j = 0; j < 4; ++j) {
                    u64 x2 = xv[j][k];
                    ffma2(acc[j][0], x2, q0.x);
                    ffma2(acc[j][1], x2, q0.y);
                    ffma2(acc[j][2], x2, q1.x);
                    ffma2(acc[j][3], x2, q1.y);
                    ffma2(acc[j][4], x2, q2.x);
                    ffma2(acc[j][5], x2, q2.y);
                    ffma2(acc[j][6], x2, q3.x);
                    ffma2(acc[j][7], x2, q3.y);
                }
            }
        }
    }

    // ---- store: out[n][o][rot][h][w], 4 consecutive w per thread-pixel-group ----
    const int h = h0 + prow;
    const int wcol = w0 + pcg * 4;
#pragma unroll
    for (int q = 0; q < 8; ++q) {
        float lo0, hi0, lo1, hi1, lo2, hi2, lo3, hi3;
        unpack2(acc[0][q], lo0, hi0);
        unpack2(acc[1][q], lo1, hi1);
        unpack2(acc[2][q], lo2, hi2);
        unpack2(acc[3][q], lo3, hi3);
        int o0 = og * 16 + q * 2;
        size_t base0 =
            (((size_t)(n * OO + o0) * 8 + ROT) * (HH * WW)) + (size_t)h * WW + wcol;
        size_t base1 =
            (((size_t)(n * OO + o0 + 1) * 8 + ROT) * (HH * WW)) + (size_t)h * WW + wcol;
        *(float4*)(outg + base0) = make_float4(lo0, lo1, lo2, lo3);
        *(float4*)(outg + base1) = make_float4(hi0, hi1, hi2, hi3);
    }
}

__global__ __launch_bounds__(NTHREADS, 1)
void gconv_kernel(const float* __restrict__ xg, float* __restrict__ outg) {
    extern __shared__ float smem[];
    float* sx = smem;                 // RCNT * CPAD = 22100 floats
    float* sw = smem + RCNT * CPAD;   // WSLICE = 20480 floats

    switch (blockIdx.y) {
        case 0: gconv_body<0>(xg, outg, sx, sw); break;
        case 1: gconv_body<1>(xg, outg, sx, sw); break;
        case 2: gconv_body<2>(xg, outg, sx, sw); break;
        case 3: gconv_body<3>(xg, outg, sx, sw); break;
        case 4: gconv_body<4>(xg, outg, sx, sw); break;
        case 5: gconv_body<5>(xg, outg, sx, sw); break;
        case 6: gconv_body<6>(xg, outg, sx, sw); break;
        case 7: gconv_body<7>(xg, outg, sx, sw); break;
    }
}

extern "C" void kernel_launch(void* const* d_in, const int* in_sizes, int n_in,
                              void* d_out, int out_size) {
    const float* x = (const float*)d_in[0];
    const float* w = (const float*)d_in[1];
    float* out = (float*)d_out;

    // one-time-per-call weight transpose into __device__ scratch (cheap, 163840 elems)
    wt_transpose<<<160, 1024>>>(w);

    int smem_bytes = (RCNT * CPAD + WSLICE) * 4;  // 170320 B
    cudaFuncSetAttribute(gconv_kernel,
                         cudaFuncAttributeMaxDynamicSharedMemorySize, smem_bytes);

    dim3 grid(16, 8, 16);  // (spatial tiles, rot, n)
    gconv_kernel<<<grid, NTHREADS, smem_bytes>>>(x, out);
}

// round 5
// speedup vs baseline: 1.4853x; 1.4853x over previous
#include <cuda_runtime.h>

// GConv: x (N=16, C=64, R=8, H=64, W=64), weight (O=64, C=64, R=8, K=5)
// out (N, O, ROT=8, H, W)
// out[n,o,rot,h,w] = sum_{r,c,k} weight[o,c,(r-rot)&7,k] * xpad[n,c,r,h+dy(k,rot),w+dx(k,rot)]
// taps: k=0 -> (0,0); k>=1 -> RING[(2k-1+rot)&7]

#define TH 8
#define TW 32
#define NTHREADS 256
#define CC 64
#define RR 8
#define OO 64
#define HH 64
#define WW 64
#define SLAB_ROWS (TH + 2)            // 10
#define SLAB_COLS (TW + 2)            // 34
#define RCNT (SLAB_ROWS * SLAB_COLS)  // 340
#define CPAD 65
#define WSLICE (64 * 5 * 64)          // 20480 floats per (s) slice

typedef unsigned long long u64;

// pre-transposed weight: wt[s][c][k][o]
__device__ float4 g_wt4[(64 * 64 * 8 * 5) / 4];

__device__ __forceinline__ u64 pack2(float x) {
    u64 r;
    asm("mov.b64 %0, {%1, %1};" : "=l"(r) : "f"(x));
    return r;
}
__device__ __forceinline__ void ffma2(u64& a, u64 x, u64 w) {
    asm("fma.rn.f32x2 %0, %1, %2, %0;" : "+l"(a) : "l"(x), "l"(w));
}
__device__ __forceinline__ void unpack2(u64 v, float& lo, float& hi) {
    asm("mov.b64 {%0, %1}, %2;" : "=f"(lo), "=f"(hi) : "l"(v));
}

__global__ void wt_transpose(const float* __restrict__ wsrc) {
    int idx = blockIdx.x * blockDim.x + threadIdx.x;  // < 163840
    int o = idx & 63;
    int k = (idx >> 6) % 5;
    int c = (idx / 320) & 63;
    int s = idx / 20480;
    // weight[o][c][s][k] -> wt[s][c][k][o]
    ((float*)g_wt4)[idx] = wsrc[o * 2560 + c * 40 + s * 5 + k];
}

// RING tables as constexpr so tap offsets are compile-time per ROT.
__device__ __forceinline__ constexpr int ring_dy(int i) {
    constexpr int t[8] = {-1, -1, -1, 0, 1, 1, 1, 0};
    return t[i & 7];
}
__device__ __forceinline__ constexpr int ring_dx(int i) {
    constexpr int t[8] = {-1, 0, 1, 1, 1, 0, -1, -1};
    return t[i & 7];
}

template <int ROT>
__device__ __forceinline__ void gconv_body(const float* __restrict__ xg,
                                           float* __restrict__ outg,
                                           float* sx, float* sw) {
    const int n = blockIdx.z;
    const int ht = blockIdx.x >> 1;
    const int wt = blockIdx.x & 1;
    const int h0 = ht * TH;
    const int w0 = wt * TW;

    const int tid = threadIdx.x;
    // Warp-uniform o-group: every LDS.128 weight load is a single 16B address
    // broadcast to 32 lanes -> 1 wavefront instead of 4.
    const int og = (tid >> 5) & 3;                    // warp % 4
    const int pg = ((tid >> 7) << 5) | (tid & 31);    // half*32 + lane : 0..63
    const int prow = pg >> 3;                          // 0..7
    const int pcg = pg & 7;                            // 0..7 -> cols pcg*4..pcg*4+3

    // Compile-time tap offsets within padded slab (row-major, stride SLAB_COLS)
    constexpr int off0 = 1 * SLAB_COLS + 1;
    constexpr int off1 = (ring_dy((1 + ROT) & 7) + 1) * SLAB_COLS + (ring_dx((1 + ROT) & 7) + 1);
    constexpr int off2 = (ring_dy((3 + ROT) & 7) + 1) * SLAB_COLS + (ring_dx((3 + ROT) & 7) + 1);
    constexpr int off3 = (ring_dy((5 + ROT) & 7) + 1) * SLAB_COLS + (ring_dx((5 + ROT) & 7) + 1);
    constexpr int off4 = (ring_dy((7 + ROT) & 7) + 1) * SLAB_COLS + (ring_dx((7 + ROT) & 7) + 1);
    const int offk[5] = {off0, off1, off2, off3, off4};

    const int bp0 = prow * SLAB_COLS + pcg * 4;  // base slab position of this thread

    u64 acc[4][8];
#pragma unroll
    for (int j = 0; j < 4; ++j)
#pragma unroll
        for (int q = 0; q < 8; ++q) acc[j][q] = 0ull;

    for (int r = 0; r < RR; ++r) {
        __syncthreads();
        // ---- stage x plane r: sx[(row*34+col)*65 + c] with zero halo ----
        {
            const float* xp = xg + ((size_t)n * CC * RR + r) * (HH * WW);
            for (int lin = tid; lin < CC * RCNT; lin += NTHREADS) {
                int c = lin / RCNT;
                int rc = lin - c * RCNT;
                int row = rc / SLAB_COLS;
                int col = rc - row * SLAB_COLS;
                int gh = h0 - 1 + row;
                int gw = w0 - 1 + col;
                float v = 0.f;
                if ((unsigned)gh < HH && (unsigned)gw < WW)
                    v = xp[(size_t)c * (RR * HH * WW) + gh * WW + gw];
                sx[rc * CPAD + c] = v;
            }
        }
        // ---- stage weight slice s = (r - rot) & 7 : sw[c][k][o] ----
        {
            int s = (r - ROT) & 7;
            const float4* wsrc4 = g_wt4 + (size_t)s * (WSLICE / 4);
            float4* sw4 = (float4*)sw;
            for (int i = tid; i < WSLICE / 4; i += NTHREADS) sw4[i] = wsrc4[i];
        }
        __syncthreads();

        const float* swb = sw + og * 16;
        const float* sxb = sx + bp0 * CPAD;
#pragma unroll 2
        for (int c = 0; c < CC; ++c) {
            // Load + pack unique x taps (compile-time offsets -> ptxas CSEs
            // overlapping positions across the 4 adjacent pixels)
            u64 xv[4][5];
#pragma unroll
            for (int j = 0; j < 4; ++j)
#pragma unroll
                for (int k = 0; k < 5; ++k)
                    xv[j][k] = pack2(sxb[(j + offk[k]) * CPAD + c]);

#pragma unroll
            for (int k = 0; k < 5; ++k) {
                const ulonglong2* wp =
                    (const ulonglong2*)(swb + c * 320 + k * 64);
                ulonglong2 q0 = wp[0];
                ulonglong2 q1 = wp[1];
                ulonglong2 q2 = wp[2];
                ulonglong2 q3 = wp[3];
#pragma unroll
                for (int j = 0; j < 4; ++j) {
                    u64 x2 = xv[j][k];
                    ffma2(acc[j][0], x2, q0.x);
                    ffma2(acc[j][1], x2, q0.y);
                    ffma2(acc[j][2], x2, q1.x);
                    ffma2(acc[j][3], x2, q1.y);
                    ffma2(acc[j][4], x2, q2.x);
                    ffma2(acc[j][5], x2, q2.y);
                    ffma2(acc[j][6], x2, q3.x);
                    ffma2(acc[j][7], x2, q3.y);
                }
            }
        }
    }

    // ---- store: out[n][o][rot][h][w], 4 consecutive w per thread-pixel-group ----
    const int h = h0 + prow;
    const int wcol = w0 + pcg * 4;
#pragma unroll
    for (int q = 0; q < 8; ++q) {
        float lo0, hi0, lo1, hi1, lo2, hi2, lo3, hi3;
        unpack2(acc[0][q], lo0, hi0);
        unpack2(acc[1][q], lo1, hi1);
        unpack2(acc[2][q], lo2, hi2);
        unpack2(acc[3][q], lo3, hi3);
        int o0 = og * 16 + q * 2;
        size_t base0 =
            (((size_t)(n * OO + o0) * 8 + ROT) * (HH * WW)) + (size_t)h * WW + wcol;
        size_t base1 =
            (((size_t)(n * OO + o0 + 1) * 8 + ROT) * (HH * WW)) + (size_t)h * WW + wcol;
        *(float4*)(outg + base0) = make_float4(lo0, lo1, lo2, lo3);
        *(float4*)(outg + base1) = make_float4(hi0, hi1, hi2, hi3);
    }
}

__global__ __launch_bounds__(NTHREADS, 1)
void gconv_kernel(const float* __restrict__ xg, float* __restrict__ outg) {
    extern __shared__ float smem[];
    float* sx = smem;                 // RCNT * CPAD = 22100 floats
    float* sw = smem + RCNT * CPAD;   // WSLICE = 20480 floats

    switch (blockIdx.y) {
        case 0: gconv_body<0>(xg, outg, sx, sw); break;
        case 1: gconv_body<1>(xg, outg, sx, sw); break;
        case 2: gconv_body<2>(xg, outg, sx, sw); break;
        case 3: gconv_body<3>(xg, outg, sx, sw); break;
        case 4: gconv_body<4>(xg, outg, sx, sw); break;
        case 5: gconv_body<5>(xg, outg, sx, sw); break;
        case 6: gconv_body<6>(xg, outg, sx, sw); break;
        case 7: gconv_body<7>(xg, outg, sx, sw); break;
    }
}

extern "C" void kernel_launch(void* const* d_in, const int* in_sizes, int n_in,
                              void* d_out, int out_size) {
    const float* x = (const float*)d_in[0];
    const float* w = (const float*)d_in[1];
    float* out = (float*)d_out;

    // one-time-per-call weight transpose into __device__ scratch (cheap, 163840 elems)
    wt_transpose<<<160, 1024>>>(w);

    int smem_bytes = (RCNT * CPAD + WSLICE) * 4;  // 170320 B
    cudaFuncSetAttribute(gconv_kernel,
                         cudaFuncAttributeMaxDynamicSharedMemorySize, smem_bytes);

    dim3 grid(16, 8, 16);  // (spatial tiles, rot, n)
    gconv_kernel<<<grid, NTHREADS, smem_bytes>>>(x, out);
}